// round 1
// baseline (speedup 1.0000x reference)
#include <cuda_runtime.h>
#include <mma.h>
#include <cstdint>
#include <cstdio>

using namespace nvcuda;

// Shapes (fixed for this problem)
//  B=32, L=256, V=10000, E=512, H=768
#define L_SEQ 256
#define NBATCH 32
#define HID 768

// ---------------- scratch (static __device__, no allocations) ----------------
__device__ float g_X[8192u * 512];            // embedded input, row m = t*32+b
__device__ float g_xp[2u * 256 * 768 * 32];   // xp[d][t][j][b]
__device__ float g_hA[2 * 768 * 32];          // h ping  [d][k][b]
__device__ float g_hB[2 * 768 * 32];          // h pong
__device__ float g_hcat[256u * 1536 * 32];    // layer output [t][c][b], c = d*768+j
__device__ float g_hmat[8192u * 1536];        // transposed [m][c] (reused as normalized input)
__device__ float g_mean[256];
__device__ float g_rstd[256];

// ---------------- embedding gather ----------------
__global__ void embed_kernel(const int* __restrict__ tokens,
                             const float* __restrict__ emb,
                             float* __restrict__ X)
{
    int m = blockIdx.x;            // m = t*32 + b
    int t = m >> 5, b = m & 31;
    int tok = tokens[b * L_SEQ + t];
    const float4* src = (const float4*)(emb + (size_t)tok * 512);
    float4* dst = (float4*)(X + (size_t)m * 512);
    dst[threadIdx.x] = src[threadIdx.x];   // 128 threads * float4 = 512 floats
}

// ---------------- zero ----------------
__global__ void zero_kernel(float* p, int n)
{
    int i = blockIdx.x * blockDim.x + threadIdx.x;
    if (i < n) p[i] = 0.f;
}

// ---------------- tf32 wmma GEMM: C = A(MxK) * W(NxK)^T (+bias) ----------------
// MODE 0: projection epilogue: row permuted to (b*256+t), + bias1, row-major out
// MODE 1: rnn layout: C[((m/32)*N + n)*32 + (m%32)], + bias1 + bias2
static const int BM = 128, BN = 64, BK = 16;

template<int MODE>
__global__ __launch_bounds__(256) void gemm_tf32(
    const float* __restrict__ A, const float* __restrict__ W,
    const float* __restrict__ bias1, const float* __restrict__ bias2,
    float* __restrict__ C, int M, int N, int K)
{
    __shared__ float smem[9216];           // union: mainloop (sA 2048 + sB 1024) / epilogue (8*32*36)
    float* sA = smem;                      // [128][16] row-major, ld=16
    float* sB = smem + BM * BK;            // [64][16]  (col-major KxN view, ld=16)

    int tid  = threadIdx.x;
    int warp = tid >> 5, lane = tid & 31;
    int wm = warp >> 1, wn = warp & 1;     // 4x2 warp grid, warp tile 32x32
    int m0 = blockIdx.y * BM, n0 = blockIdx.x * BN;

    wmma::fragment<wmma::accumulator, 16, 16, 8, float> acc[2][2];
#pragma unroll
    for (int i = 0; i < 2; i++)
#pragma unroll
        for (int j = 0; j < 2; j++) wmma::fill_fragment(acc[i][j], 0.0f);

    for (int k0 = 0; k0 < K; k0 += BK) {
        // stage A tile: 128x16 floats
        for (int i = tid; i < BM * BK / 4; i += 256) {
            int m = i >> 2, c = i & 3;
            *(float4*)&sA[m * BK + c * 4] =
                *(const float4*)&A[(size_t)(m0 + m) * K + k0 + c * 4];
        }
        // stage W tile: 64x16 (guard N)
        for (int i = tid; i < BN * BK / 4; i += 256) {
            int n = i >> 2, c = i & 3;
            float4 v = make_float4(0.f, 0.f, 0.f, 0.f);
            if (n0 + n < N)
                v = *(const float4*)&W[(size_t)(n0 + n) * K + k0 + c * 4];
            *(float4*)&sB[n * BK + c * 4] = v;
        }
        __syncthreads();

#pragma unroll
        for (int kk = 0; kk < BK; kk += 8) {
            wmma::fragment<wmma::matrix_a, 16, 16, 8, wmma::precision::tf32, wmma::row_major> af[2];
            wmma::fragment<wmma::matrix_b, 16, 16, 8, wmma::precision::tf32, wmma::col_major> bf[2];
#pragma unroll
            for (int i = 0; i < 2; i++) {
                wmma::load_matrix_sync(af[i], sA + (wm * 32 + i * 16) * BK + kk, BK);
#pragma unroll
                for (int e = 0; e < af[i].num_elements; e++)
                    af[i].x[e] = wmma::__float_to_tf32(af[i].x[e]);
            }
#pragma unroll
            for (int j = 0; j < 2; j++) {
                wmma::load_matrix_sync(bf[j], sB + (wn * 32 + j * 16) * BK + kk, BK);
#pragma unroll
                for (int e = 0; e < bf[j].num_elements; e++)
                    bf[j].x[e] = wmma::__float_to_tf32(bf[j].x[e]);
            }
#pragma unroll
            for (int i = 0; i < 2; i++)
#pragma unroll
                for (int j = 0; j < 2; j++)
                    wmma::mma_sync(acc[i][j], af[i], bf[j], acc[i][j]);
        }
        __syncthreads();
    }

    // epilogue: stage each warp's 32x32 tile in smem (per-warp region, ld=36)
    float* sCw = smem + warp * 32 * 36;
#pragma unroll
    for (int i = 0; i < 2; i++)
#pragma unroll
        for (int j = 0; j < 2; j++)
            wmma::store_matrix_sync(sCw + (i * 16) * 36 + j * 16, acc[i][j], 36,
                                    wmma::mem_row_major);
    __syncwarp();

    if (MODE == 0) {
        // projection: out[b*256+t][n], lanes walk n (coalesced)
        for (int it = 0; it < 32; ++it) {
            int ml = it, nl = lane;
            int n = n0 + wn * 32 + nl;
            if (n < N) {
                int m = m0 + wm * 32 + ml;
                float v = sCw[ml * 36 + nl] + bias1[n];
                int row = (m & 31) * L_SEQ + (m >> 5);
                C[(size_t)row * N + n] = v;
            }
        }
    } else {
        // rnn layout: C[(t*N + n)*32 + b], lanes walk b (coalesced)
        for (int it = 0; it < 32; ++it) {
            int nl = it, ml = lane;
            int n = n0 + wn * 32 + nl;
            int m = m0 + wm * 32 + ml;
            float v = sCw[ml * 36 + nl] + bias1[n] + bias2[n];
            int t = m >> 5;
            C[((size_t)t * N + n) * 32 + (m & 31)] = v;
        }
    }
}

// ---------------- one recurrence step, both directions ----------------
// grid = 192 blocks: d = bx/96, 8 j's per block; 8 warps split K (96 each); lane = batch
__global__ __launch_bounds__(256) void rnn_step(
    const float* __restrict__ xp,     // [2][256][768][32]
    const float* __restrict__ hprev,  // [2][768][32]
    float* __restrict__ hnew,         // [2][768][32]
    const float* __restrict__ Whh,    // [2][768][768]
    float* __restrict__ hcat,         // [256][1536][32]
    int s)
{
    int bx = blockIdx.x;
    int d  = bx / 96;
    int j0 = (bx % 96) * 8;
    int t_eff = d ? (L_SEQ - 1 - s) : s;
    int w = threadIdx.x >> 5, lane = threadIdx.x & 31;

    const float* hp = hprev + d * HID * 32;
    const float* Wd = Whh + (size_t)d * HID * HID;

    float acc[8];
#pragma unroll
    for (int jj = 0; jj < 8; jj++) acc[jj] = 0.f;

    int k0 = w * 96;
    for (int k = k0; k < k0 + 96; k += 4) {
        float h0 = hp[(k + 0) * 32 + lane];
        float h1 = hp[(k + 1) * 32 + lane];
        float h2 = hp[(k + 2) * 32 + lane];
        float h3 = hp[(k + 3) * 32 + lane];
#pragma unroll
        for (int jj = 0; jj < 8; jj++) {
            float4 w4 = *(const float4*)&Wd[(size_t)(j0 + jj) * HID + k];
            acc[jj] += w4.x * h0 + w4.y * h1 + w4.z * h2 + w4.w * h3;
        }
    }

    __shared__ float part[8][8][32];
#pragma unroll
    for (int jj = 0; jj < 8; jj++) part[w][jj][lane] = acc[jj];
    __syncthreads();

    int jj = w;   // 8 j's x 32 lanes = 256 outputs
    float sum = 0.f;
#pragma unroll
    for (int ww = 0; ww < 8; ww++) sum += part[ww][jj][lane];

    int j = j0 + jj;
    float v = tanhf(sum + xp[(((size_t)d * L_SEQ + t_eff) * HID + j) * 32 + lane]);
    hnew[(d * HID + j) * 32 + lane] = v;
    hcat[(((size_t)t_eff) * 1536 + d * HID + j) * 32 + lane] = v;
}

// ---------------- transpose [t][c][b] -> [t*32+b][c] ----------------
__global__ void transpose_cb(const float* __restrict__ src, float* __restrict__ dst)
{
    __shared__ float tile[32][33];
    int cg = blockIdx.x * 32;
    int t  = blockIdx.y;
    int x  = threadIdx.x;
    for (int y = threadIdx.y; y < 32; y += 8)
        tile[y][x] = src[((size_t)t * 1536 + cg + y) * 32 + x];
    __syncthreads();
    for (int y = threadIdx.y; y < 32; y += 8)
        dst[((size_t)t * 32 + y) * 1536 + cg + x] = tile[x][y];
}

// ---------------- BN stats per t over (c,b) ----------------
__global__ __launch_bounds__(256) void bn_stats(const float* __restrict__ hcat,
                                                float* __restrict__ mean,
                                                float* __restrict__ rstd)
{
    int t = blockIdx.x, tid = threadIdx.x;
    const float* p = hcat + (size_t)t * 49152;
    float s = 0.f, q = 0.f;
    for (int i = tid; i < 49152; i += 256) { float v = p[i]; s += v; q += v * v; }
    __shared__ float rs[256], rq[256];
    rs[tid] = s; rq[tid] = q;
    __syncthreads();
    for (int o = 128; o > 0; o >>= 1) {
        if (tid < o) { rs[tid] += rs[tid + o]; rq[tid] += rq[tid + o]; }
        __syncthreads();
    }
    if (tid == 0) {
        float m = rs[0] * (1.f / 49152.f);
        float v = rq[0] * (1.f / 49152.f) - m * m;
        mean[t] = m;
        rstd[t] = rsqrtf(v + 1e-5f);
    }
}

// ---------------- fused transpose + BN normalize ----------------
__global__ void transpose_norm(const float* __restrict__ src, float* __restrict__ dst,
                               const float* __restrict__ mean, const float* __restrict__ rstd,
                               const float* __restrict__ gamma, const float* __restrict__ beta)
{
    __shared__ float tile[32][33];
    int cg = blockIdx.x * 32;
    int t  = blockIdx.y;
    int x  = threadIdx.x;
    float mu = mean[t];
    float sc = rstd[t] * gamma[t];
    float bb = beta[t];
    for (int y = threadIdx.y; y < 32; y += 8)
        tile[y][x] = src[((size_t)t * 1536 + cg + y) * 32 + x];
    __syncthreads();
    for (int y = threadIdx.y; y < 32; y += 8)
        dst[((size_t)t * 32 + y) * 1536 + cg + x] = (tile[x][y] - mu) * sc + bb;
}

// ---------------- launch ----------------
extern "C" void kernel_launch(void* const* d_in, const int* in_sizes, int n_in,
                              void* d_out, int out_size)
{
    const int*   tokens  = (const int*)d_in[0];
    const float* emb     = (const float*)d_in[1];
    const float* w_ih_l0 = (const float*)d_in[2];
    const float* w_hh_l0 = (const float*)d_in[3];
    const float* b_ih_l0 = (const float*)d_in[4];
    const float* b_hh_l0 = (const float*)d_in[5];
    const float* w_ih_l1 = (const float*)d_in[6];
    const float* w_hh_l1 = (const float*)d_in[7];
    const float* b_ih_l1 = (const float*)d_in[8];
    const float* b_hh_l1 = (const float*)d_in[9];
    const float* gamma   = (const float*)d_in[10];
    const float* beta    = (const float*)d_in[11];
    const float* lin_w   = (const float*)d_in[12];
    const float* lin_b   = (const float*)d_in[13];
    float* out = (float*)d_out;

    float *X, *xp, *hA, *hB, *hcat, *hmat, *mean, *rstd;
    cudaGetSymbolAddress((void**)&X,    g_X);
    cudaGetSymbolAddress((void**)&xp,   g_xp);
    cudaGetSymbolAddress((void**)&hA,   g_hA);
    cudaGetSymbolAddress((void**)&hB,   g_hB);
    cudaGetSymbolAddress((void**)&hcat, g_hcat);
    cudaGetSymbolAddress((void**)&hmat, g_hmat);
    cudaGetSymbolAddress((void**)&mean, g_mean);
    cudaGetSymbolAddress((void**)&rstd, g_rstd);

    // 1) embed
    embed_kernel<<<8192, 128>>>(tokens, emb, X);

    // 2) layer 0 input GEMM: xp[d] = X @ w_ih_l0[d]^T + b_ih + b_hh  (rnn layout)
    dim3 g1(HID / BN, 8192 / BM);
    for (int d = 0; d < 2; ++d)
        gemm_tf32<1><<<g1, 256>>>(X, w_ih_l0 + (size_t)d * HID * 512,
                                  b_ih_l0 + d * HID, b_hh_l0 + d * HID,
                                  xp + (size_t)d * L_SEQ * HID * 32, 8192, HID, 512);

    // 3) layer 0 recurrence (both dirs per step)
    zero_kernel<<<192, 256>>>(hA, 2 * HID * 32);
    for (int s = 0; s < L_SEQ; ++s) {
        float* hp = (s & 1) ? hB : hA;
        float* hn = (s & 1) ? hA : hB;
        rnn_step<<<192, 256>>>(xp, hp, hn, w_hh_l0, hcat, s);
    }

    // 4) transpose layer-0 output to GEMM layout
    transpose_cb<<<dim3(48, 256), dim3(32, 8)>>>(hcat, hmat);

    // 5) layer 1 input GEMM
    for (int d = 0; d < 2; ++d)
        gemm_tf32<1><<<g1, 256>>>(hmat, w_ih_l1 + (size_t)d * HID * 1536,
                                  b_ih_l1 + d * HID, b_hh_l1 + d * HID,
                                  xp + (size_t)d * L_SEQ * HID * 32, 8192, HID, 1536);

    // 6) layer 1 recurrence
    zero_kernel<<<192, 256>>>(hA, 2 * HID * 32);
    for (int s = 0; s < L_SEQ; ++s) {
        float* hp = (s & 1) ? hB : hA;
        float* hn = (s & 1) ? hA : hB;
        rnn_step<<<192, 256>>>(xp, hp, hn, w_hh_l1, hcat, s);
    }

    // 7) BN stats + fused normalize/transpose
    bn_stats<<<256, 256>>>(hcat, mean, rstd);
    transpose_norm<<<dim3(48, 256), dim3(32, 8)>>>(hcat, hmat, mean, rstd, gamma, beta);

    // 8) projection: out = xn @ lin_w^T + lin_b  (rows permuted to b*256+t)
    gemm_tf32<0><<<dim3((10000 + BN - 1) / BN, 8192 / BM), 256>>>(
        hmat, lin_w, lin_b, nullptr, out, 8192, 10000, 1536);
}

// round 2
// speedup vs baseline: 1.4293x; 1.4293x over previous
#include <cuda_runtime.h>
#include <mma.h>
#include <cstdint>
#include <cstdio>

using namespace nvcuda;

#define L_SEQ 256
#define HID 768

// ---------------- scratch ----------------
__device__ float g_X[8192u * 512];            // embedded input, row m = t*32+b
__device__ float g_xp[2u * 256 * 768 * 32];   // xp[d][t][j][b]
__device__ float g_h[2][2][32][768];          // ping-pong h [pp][d][b][k]
__device__ float g_hcat[256u * 1536 * 32];    // layer output [t][c][b]
__device__ float g_hmat[8192u * 1536];        // [m][c] GEMM layout
__device__ float g_mean[256];
__device__ float g_rstd[256];
__device__ unsigned g_cnt[2];
__device__ unsigned g_gen[2];

// ---------------- helpers ----------------
__device__ __forceinline__ float tf32r(float x) {
    float r;
    asm("cvt.rna.tf32.f32 %0, %1;" : "=f"(r) : "f"(x));
    return r;
}

__device__ __forceinline__ void cp_async16(void* sdst, const void* gsrc, bool pred) {
    uint32_t sa = (uint32_t)__cvta_generic_to_shared(sdst);
    int sz = pred ? 16 : 0;
    asm volatile("cp.async.cg.shared.global [%0], [%1], 16, %2;\n"
                 :: "r"(sa), "l"(gsrc), "r"(sz));
}
__device__ __forceinline__ void cp_commit() { asm volatile("cp.async.commit_group;\n"); }
template<int N> __device__ __forceinline__ void cp_wait() {
    asm volatile("cp.async.wait_group %0;\n" :: "n"(N));
}

// ---------------- embedding gather ----------------
__global__ void embed_kernel(const int* __restrict__ tokens,
                             const float* __restrict__ emb,
                             float* __restrict__ X)
{
    int m = blockIdx.x, t = m >> 5, b = m & 31;
    int tok = tokens[b * L_SEQ + t];
    const float4* src = (const float4*)(emb + (size_t)tok * 512);
    float4* dst = (float4*)(X + (size_t)m * 512);
    dst[threadIdx.x] = src[threadIdx.x];
}

// ---------------- reset for persistent recurrence ----------------
__global__ void rnn_reset()
{
    int i = blockIdx.x * blockDim.x + threadIdx.x;   // 96*512 = 49152
    float* h0 = &g_h[0][0][0][0];
    if (i < 2 * 32 * 768) h0[i] = 0.f;
    if (i == 0) { g_cnt[0] = 0; g_cnt[1] = 0; g_gen[0] = 0; g_gen[1] = 0; }
}

// ================= GEMM v2: tf32 wmma, cp.async double-buffered =================
// C = A(MxK) @ W(NxK)^T (+bias).  MODE 0: projection out[(b*256+t)][n] + b1
//                                 MODE 1: rnn layout C[(t*N+n)*32+b] + b1 + b2
#define GBM 128
#define GBN 128
#define GBK 32
#define GLD 36            // smem ld (floats)

template<int MODE>
__global__ __launch_bounds__(256, 2) void gemm2(
    const float* __restrict__ A, const float* __restrict__ W,
    const float* __restrict__ b1, const float* __restrict__ b2,
    float* __restrict__ C, int M, int N, int K)
{
    extern __shared__ float sm[];
    float* sA = sm;                       // [2][128][36]
    float* sB = sm + 2 * GBM * GLD;       // [2][128][36]

    int tid = threadIdx.x, warp = tid >> 5, lane = tid & 31;
    int wm = warp >> 2, wn = warp & 3;    // 2x4 warp grid, warp tile 64x32
    int m0 = blockIdx.y * GBM, n0 = blockIdx.x * GBN;
    int ntiles = K / GBK;

    auto loadtile = [&](int kt, int buf) {
        int k0 = kt * GBK;
#pragma unroll
        for (int i = 0; i < 4; i++) {
            int ch = tid + i * 256, r = ch >> 3, cg = ch & 7;
            cp_async16(&sA[((size_t)buf * GBM + r) * GLD + cg * 4],
                       A + (size_t)(m0 + r) * K + k0 + cg * 4, true);
        }
#pragma unroll
        for (int i = 0; i < 4; i++) {
            int ch = tid + i * 256, r = ch >> 3, cg = ch & 7;
            int n = n0 + r;
            bool p = (n < N);
            const float* src = W + (size_t)(p ? n : 0) * K + k0 + cg * 4;
            cp_async16(&sB[((size_t)buf * GBM + r) * GLD + cg * 4], src, p);
        }
    };

    wmma::fragment<wmma::accumulator, 16, 16, 8, float> acc[4][2];
#pragma unroll
    for (int i = 0; i < 4; i++)
#pragma unroll
        for (int j = 0; j < 2; j++) wmma::fill_fragment(acc[i][j], 0.0f);

    loadtile(0, 0);
    cp_commit();

    for (int kt = 0; kt < ntiles; kt++) {
        int cur = kt & 1;
        if (kt + 1 < ntiles) { loadtile(kt + 1, cur ^ 1); cp_commit(); cp_wait<1>(); }
        else                 { cp_commit(); cp_wait<0>(); }
        __syncthreads();

        const float* A0 = &sA[((size_t)cur * GBM + wm * 64) * GLD];
        const float* B0 = &sB[((size_t)cur * GBM + wn * 32) * GLD];
#pragma unroll
        for (int kk = 0; kk < 4; kk++) {
            wmma::fragment<wmma::matrix_a, 16, 16, 8, wmma::precision::tf32, wmma::row_major> af[4];
            wmma::fragment<wmma::matrix_b, 16, 16, 8, wmma::precision::tf32, wmma::col_major> bf[2];
#pragma unroll
            for (int i = 0; i < 4; i++) {
                wmma::load_matrix_sync(af[i], A0 + (size_t)i * 16 * GLD + kk * 8, GLD);
#pragma unroll
                for (int e = 0; e < af[i].num_elements; e++)
                    af[i].x[e] = wmma::__float_to_tf32(af[i].x[e]);
            }
#pragma unroll
            for (int j = 0; j < 2; j++) {
                wmma::load_matrix_sync(bf[j], B0 + (size_t)j * 16 * GLD + kk * 8, GLD);
#pragma unroll
                for (int e = 0; e < bf[j].num_elements; e++)
                    bf[j].x[e] = wmma::__float_to_tf32(bf[j].x[e]);
            }
#pragma unroll
            for (int i = 0; i < 4; i++)
#pragma unroll
                for (int j = 0; j < 2; j++)
                    wmma::mma_sync(acc[i][j], af[i], bf[j], acc[i][j]);
        }
        __syncthreads();
    }

    // epilogue: per-warp 64x32 staging tile, ld 36
    float* sC = sm + (size_t)warp * 64 * GLD;
#pragma unroll
    for (int i = 0; i < 4; i++)
#pragma unroll
        for (int j = 0; j < 2; j++)
            wmma::store_matrix_sync(sC + (size_t)i * 16 * GLD + j * 16, acc[i][j], GLD,
                                    wmma::mem_row_major);
    __syncwarp();

    if (MODE == 0) {
        int n = n0 + wn * 32 + lane;
        if (n < N) {
            float bv = b1[n];
#pragma unroll 4
            for (int ml = 0; ml < 64; ml++) {
                int m = m0 + wm * 64 + ml;
                float v = sC[ml * GLD + lane] + bv;
                int row = (m & 31) * L_SEQ + (m >> 5);
                C[(size_t)row * N + n] = v;
            }
        }
    } else {
#pragma unroll
        for (int half = 0; half < 2; half++) {
            int ml = half * 32 + lane;
            int m = m0 + wm * 64 + ml;
            int t = m >> 5, b = m & 31;
#pragma unroll 4
            for (int nl = 0; nl < 32; nl++) {
                int n = n0 + wn * 32 + nl;
                float v = sC[ml * GLD + nl] + b1[n] + b2[n];
                C[((size_t)t * N + n) * 32 + b] = v;
            }
        }
    }
}

// ================= persistent bi-RNN layer =================
// 96 blocks: d = blk/48, 16-wide j slice per block. 128 threads (4 warps, k-split).
// W slice pre-split (tf32 hi/lo) resident in smem. h in global, 3xTF32 mma.
__global__ __launch_bounds__(128, 1) void rnn_layer(
    const float* __restrict__ xp,    // [2][256][768][32]
    const float* __restrict__ Whh,   // [2][768][768]
    float* __restrict__ hcat)        // [256][1536][32]
{
    extern __shared__ float sm[];
    float* sWhi = sm;                      // [16][776]  (j-major)
    float* sWlo = sm + 16 * 776;
    float* sPart = sm + 2 * 16 * 776;      // [4 warps][2 mfrag][16][16]

    int blk = blockIdx.x;
    int d = blk / 48, j0 = (blk % 48) * 16;
    int tid = threadIdx.x, w = tid >> 5;

    // fill W slice, pre-split into tf32 hi/lo
    const float* Wd = Whh + (size_t)d * HID * HID;
    for (int i = tid; i < 16 * 192; i += 128) {
        int j = i / 192, c = i % 192;
        float4 v = *(const float4*)&Wd[(size_t)(j0 + j) * HID + c * 4];
        float vv[4] = {v.x, v.y, v.z, v.w};
#pragma unroll
        for (int q = 0; q < 4; q++) {
            float hi = tf32r(vv[q]);
            float lo = tf32r(vv[q] - hi);
            sWhi[j * 776 + c * 4 + q] = hi;
            sWlo[j * 776 + c * 4 + q] = lo;
        }
    }
    __syncthreads();

    const float* xpd = xp + (size_t)d * L_SEQ * HID * 32;
    int b = tid >> 2, jq = (tid & 3) * 4;

    for (int s = 0; s < L_SEQ; s++) {
        int t = d ? (L_SEQ - 1 - s) : s;
        const float* hp = &g_h[s & 1][d][0][0];
        float* hn = &g_h[(s + 1) & 1][d][0][0];

        wmma::fragment<wmma::accumulator, 16, 16, 8, float> acc[2];
        wmma::fill_fragment(acc[0], 0.0f);
        wmma::fill_fragment(acc[1], 0.0f);

        int kbase = w * 192;
#pragma unroll 4
        for (int kt = 0; kt < 24; kt++) {
            int k = kbase + kt * 8;
            wmma::fragment<wmma::matrix_a, 16, 16, 8, wmma::precision::tf32, wmma::row_major> ahi[2], alo[2];
#pragma unroll
            for (int i = 0; i < 2; i++) {
                wmma::load_matrix_sync(ahi[i], hp + (size_t)(i * 16) * HID + k, HID);
#pragma unroll
                for (int e = 0; e < ahi[i].num_elements; e++) {
                    float x = ahi[i].x[e];
                    float hi = tf32r(x);
                    alo[i].x[e] = tf32r(x - hi);
                    ahi[i].x[e] = hi;
                }
            }
            wmma::fragment<wmma::matrix_b, 16, 16, 8, wmma::precision::tf32, wmma::col_major> bhi, blo;
            wmma::load_matrix_sync(bhi, sWhi + k, 776);
            wmma::load_matrix_sync(blo, sWlo + k, 776);
#pragma unroll
            for (int i = 0; i < 2; i++) {
                wmma::mma_sync(acc[i], ahi[i], bhi, acc[i]);
                wmma::mma_sync(acc[i], ahi[i], blo, acc[i]);
                wmma::mma_sync(acc[i], alo[i], bhi, acc[i]);
            }
        }
#pragma unroll
        for (int i = 0; i < 2; i++)
            wmma::store_matrix_sync(&sPart[(size_t)((w * 2 + i) * 16) * 16], acc[i], 16,
                                    wmma::mem_row_major);
        __syncthreads();

        // finalize: 4 j's per thread at fixed b
        float4 hv;
        float vals[4];
#pragma unroll
        for (int q = 0; q < 4; q++) {
            int j = jq + q;
            float ssum = 0.f;
#pragma unroll
            for (int ww = 0; ww < 4; ww++)
                ssum += sPart[(size_t)(((ww * 2 + (b >> 4)) * 16) + (b & 15)) * 16 + j];
            float val = tanhf(ssum + xpd[((size_t)t * HID + j0 + j) * 32 + b]);
            vals[q] = val;
            hcat[((size_t)t * 1536 + d * HID + j0 + j) * 32 + b] = val;
        }
        hv.x = vals[0]; hv.y = vals[1]; hv.z = vals[2]; hv.w = vals[3];
        *(float4*)&hn[(size_t)b * HID + j0 + jq] = hv;

        __threadfence();
        __syncthreads();
        if (tid == 0) {
            unsigned a = atomicAdd(&g_cnt[d], 1u);
            if (a == 47u) {
                g_cnt[d] = 0u;
                __threadfence();
                atomicExch(&g_gen[d], (unsigned)(s + 1));
            } else {
                while (atomicAdd(&g_gen[d], 0u) < (unsigned)(s + 1)) __nanosleep(64);
            }
            __threadfence();
        }
        __syncthreads();
    }
}

// ---------------- transpose [t][c][b] -> [t*32+b][c] ----------------
__global__ void transpose_cb(const float* __restrict__ src, float* __restrict__ dst)
{
    __shared__ float tile[32][33];
    int cg = blockIdx.x * 32, t = blockIdx.y, x = threadIdx.x;
    for (int y = threadIdx.y; y < 32; y += 8)
        tile[y][x] = src[((size_t)t * 1536 + cg + y) * 32 + x];
    __syncthreads();
    for (int y = threadIdx.y; y < 32; y += 8)
        dst[((size_t)t * 32 + y) * 1536 + cg + x] = tile[x][y];
}

// ---------------- BN stats ----------------
__global__ __launch_bounds__(256) void bn_stats(const float* __restrict__ hcat,
                                                float* __restrict__ mean,
                                                float* __restrict__ rstd)
{
    int t = blockIdx.x, tid = threadIdx.x;
    const float* p = hcat + (size_t)t * 49152;
    float s = 0.f, q = 0.f;
    for (int i = tid; i < 49152; i += 256) { float v = p[i]; s += v; q += v * v; }
    __shared__ float rs[256], rq[256];
    rs[tid] = s; rq[tid] = q;
    __syncthreads();
    for (int o = 128; o > 0; o >>= 1) {
        if (tid < o) { rs[tid] += rs[tid + o]; rq[tid] += rq[tid + o]; }
        __syncthreads();
    }
    if (tid == 0) {
        float m = rs[0] * (1.f / 49152.f);
        float v = rq[0] * (1.f / 49152.f) - m * m;
        mean[t] = m;
        rstd[t] = rsqrtf(v + 1e-5f);
    }
}

// ---------------- fused transpose + BN normalize ----------------
__global__ void transpose_norm(const float* __restrict__ src, float* __restrict__ dst,
                               const float* __restrict__ mean, const float* __restrict__ rstd,
                               const float* __restrict__ gamma, const float* __restrict__ beta)
{
    __shared__ float tile[32][33];
    int cg = blockIdx.x * 32, t = blockIdx.y, x = threadIdx.x;
    float mu = mean[t];
    float sc = rstd[t] * gamma[t];
    float bb = beta[t];
    for (int y = threadIdx.y; y < 32; y += 8)
        tile[y][x] = src[((size_t)t * 1536 + cg + y) * 32 + x];
    __syncthreads();
    for (int y = threadIdx.y; y < 32; y += 8)
        dst[((size_t)t * 32 + y) * 1536 + cg + x] = (tile[x][y] - mu) * sc + bb;
}

// ---------------- launch ----------------
extern "C" void kernel_launch(void* const* d_in, const int* in_sizes, int n_in,
                              void* d_out, int out_size)
{
    const int*   tokens  = (const int*)d_in[0];
    const float* emb     = (const float*)d_in[1];
    const float* w_ih_l0 = (const float*)d_in[2];
    const float* w_hh_l0 = (const float*)d_in[3];
    const float* b_ih_l0 = (const float*)d_in[4];
    const float* b_hh_l0 = (const float*)d_in[5];
    const float* w_ih_l1 = (const float*)d_in[6];
    const float* w_hh_l1 = (const float*)d_in[7];
    const float* b_ih_l1 = (const float*)d_in[8];
    const float* b_hh_l1 = (const float*)d_in[9];
    const float* gamma   = (const float*)d_in[10];
    const float* beta    = (const float*)d_in[11];
    const float* lin_w   = (const float*)d_in[12];
    const float* lin_b   = (const float*)d_in[13];
    float* out = (float*)d_out;

    float *X, *xp, *hcat, *hmat, *mean, *rstd;
    cudaGetSymbolAddress((void**)&X,    g_X);
    cudaGetSymbolAddress((void**)&xp,   g_xp);
    cudaGetSymbolAddress((void**)&hcat, g_hcat);
    cudaGetSymbolAddress((void**)&hmat, g_hmat);
    cudaGetSymbolAddress((void**)&mean, g_mean);
    cudaGetSymbolAddress((void**)&rstd, g_rstd);

    const int GEMM_SMEM = 2 * 2 * GBM * GLD * 4;   // 73728 B
    const int RNN_SMEM  = 114 * 1024;              // force 1 block/SM (uses ~105KB)
    cudaFuncSetAttribute(gemm2<0>, cudaFuncAttributeMaxDynamicSharedMemorySize, GEMM_SMEM);
    cudaFuncSetAttribute(gemm2<1>, cudaFuncAttributeMaxDynamicSharedMemorySize, GEMM_SMEM);
    cudaFuncSetAttribute(rnn_layer, cudaFuncAttributeMaxDynamicSharedMemorySize, RNN_SMEM);

    // 1) embed
    embed_kernel<<<8192, 128>>>(tokens, emb, X);

    // 2) layer 0 input GEMMs (rnn layout)
    dim3 g1(HID / GBN, 8192 / GBM);
    for (int d = 0; d < 2; ++d)
        gemm2<1><<<g1, 256, GEMM_SMEM>>>(X, w_ih_l0 + (size_t)d * HID * 512,
                                         b_ih_l0 + d * HID, b_hh_l0 + d * HID,
                                         xp + (size_t)d * L_SEQ * HID * 32, 8192, HID, 512);

    // 3) layer 0 recurrence (persistent)
    rnn_reset<<<96, 512>>>();
    rnn_layer<<<96, 128, RNN_SMEM>>>(xp, w_hh_l0, hcat);

    // 4) transpose to GEMM layout
    transpose_cb<<<dim3(48, 256), dim3(32, 8)>>>(hcat, hmat);

    // 5) layer 1 input GEMMs
    for (int d = 0; d < 2; ++d)
        gemm2<1><<<g1, 256, GEMM_SMEM>>>(hmat, w_ih_l1 + (size_t)d * HID * 1536,
                                         b_ih_l1 + d * HID, b_hh_l1 + d * HID,
                                         xp + (size_t)d * L_SEQ * HID * 32, 8192, HID, 1536);

    // 6) layer 1 recurrence (persistent)
    rnn_reset<<<96, 512>>>();
    rnn_layer<<<96, 128, RNN_SMEM>>>(xp, w_hh_l1, hcat);

    // 7) BN stats + fused normalize/transpose
    bn_stats<<<256, 256>>>(hcat, mean, rstd);
    transpose_norm<<<dim3(48, 256), dim3(32, 8)>>>(hcat, hmat, mean, rstd, gamma, beta);

    // 8) projection
    gemm2<0><<<dim3((10000 + GBN - 1) / GBN, 8192 / GBM), 256, GEMM_SMEM>>>(
        hmat, lin_w, lin_b, nullptr, out, 8192, 10000, 1536);
}